// round 7
// baseline (speedup 1.0000x reference)
#include <cuda_runtime.h>
#include <stdint.h>

// ---------------------------------------------------------------------------
// ImaginationMPCV2 — bit-matching model: jax on the Grace CPU (aarch64),
// XLA:CPU strict middle-end (no fast-math FMF) BUT backend FPOpFusion::Fast
// (cpu_compiler sets AllowFPOpFusion=Fast unconditionally) -> aarch64 ISel
// greedily fuses fmul+fadd/fsub via the generic DAG rules:
//   (fadd (fmul x,y), z) -> fma(x,y,z)        [first operand preferred]
//   (fadd x, (fmul y,z)) -> fma(y,z,x)
//   (fsub x, (fmul y,z)) -> fma(-y,z,x)
// Trig = scalar glibc sinf/cosf (optimized-routines, aarch64
// TOINT_INTRINSICS: frintn ties-to-even), ported bit-exactly.
// Reduce-based sums (terminal costs) carry an unfoldable fadd(+0,x) wrapper,
// flipping fusion onto the SECOND square: fma(e2,e2, e1*e1).
// ---------------------------------------------------------------------------

#define EPS_F          1e-5f
#define TWO_EPS_F      2e-5f
#define DT_F           0.02f
#define HALF_DT_F      0.01f
#define HALF_DT_FR_F   0.001f
#define PI_F           3.14159265358979323846f
#define TWO_PI_F       6.28318530717958647692f
#define T_STEPS        100

// ---- glibc sincosf constants (optimized-routines, table entry 0) ----
#define HPI_INV_D  0x1.45F306DC9C883p-1   // 2/pi
#define HPI_D      0x1.921FB54442D18p0    // pi/2
#define S1_D      -0x1.555545995a603p-3
#define S2_D       0x1.1107605230bc4p-7
#define S3_D      -0x1.994eb3774cf24p-13
#define C0_D       0x1p0
#define C1_D      -0x1.ffffffd0c621cp-2
#define C2_D       0x1.55553e1068f19p-5
#define C3_D      -0x1.6c087e89a359dp-10
#define C4_D       0x1.99343027bf8c3p-16

// sine-branch polynomial (glibc sinf_poly, n even), fma-contracted.
__device__ __forceinline__ float sinpoly_mag(double xr, double x2)
{
    double x3 = xr * x2;
    double s1 = fma(x2, S3_D, S2_D);
    double x7 = x3 * x2;
    double s  = fma(x3, S1_D, xr);
    return (float)fma(x7, s1, s);
}

// cosine-branch polynomial (glibc sinf_poly, n odd, entry-0 coefficients).
__device__ __forceinline__ float cospoly_mag(double x2)
{
    double x4 = x2 * x2;
    double c2 = fma(x2, C4_D, C3_D);
    double c1 = fma(x2, C1_D, C0_D);
    double x6 = x4 * x2;
    double c  = fma(x4, C2_D, c1);
    return (float)fma(x6, c2, c);
}

// glibc reduce_fast, aarch64 TOINT_INTRINSICS: frintn/fcvtns = ties-to-even.
__device__ __forceinline__ double reduce_fast_g(double x, int* np)
{
    double r  = x * HPI_INV_D;
    double rr = rint(r);                 // ties-to-even (frintn)
    *np = __double2int_rn(r);            // ties-to-even convert (fcvtns)
    return fma(-rr, HPI_D, x);
}

// glibc sinf+cosf of one argument (bit-exact to the separate scalar calls;
// the reduction they'd each perform is value-identical, so sharing is safe).
__device__ __forceinline__ void glibc_sincosf(float y, float* so, float* co)
{
    uint32_t ax = __float_as_uint(y) & 0x7fffffffu;
    double x = (double)y;

    if (ax < 0x3F400000u) {                       // |y| < pi/4 band
        if (ax < 0x39800000u) { *so = y; *co = 1.0f; return; }
        double x2 = x * x;
        *so = sinpoly_mag(x, x2);
        *co = cospoly_mag(x2);
        return;
    }
    if (ax < 0x42F00000u) {                       // |y| < 120 band
        int n;
        double xr = reduce_fast_g(x, &n);
        double x2 = xr * xr;
        float sm = sinpoly_mag(xr, x2);
        float cm = cospoly_mag(x2);
        // sinf: even n -> sign[n&3]*sinpoly; odd n -> table(n&2) cospoly
        if (n & 1) *so = (n & 2) ? -cm : cm;
        else       *so = (n & 2) ? -sm : sm;
        // cosf: uses n+1
        if (n & 1) *co = (((n + 1) & 3) == 2) ? -sm : sm;
        else       *co = ((n + 1) & 2) ? -cm : cm;
        return;
    }
    double ds, dc;                                // unreachable here
    sincos(x, &ds, &dc);
    *so = (float)ds; *co = (float)dc;
}

__device__ __forceinline__ float glibc_cosf(float y)
{
    uint32_t ax = __float_as_uint(y) & 0x7fffffffu;
    double x = (double)y;

    if (ax < 0x3F400000u) {
        if (ax < 0x39800000u) return 1.0f;
        return cospoly_mag(x * x);
    }
    if (ax < 0x42F00000u) {
        int n;
        double xr = reduce_fast_g(x, &n);
        double x2 = xr * xr;
        if (n & 1) {
            float sm = sinpoly_mag(xr, x2);
            return (((n + 1) & 3) == 2) ? -sm : sm;
        } else {
            float cm = cospoly_mag(x2);
            return ((n + 1) & 2) ? -cm : cm;
        }
    }
    return (float)cos(x);
}

// ---- Hamiltonian with aarch64-backend fusion pattern ----
//   denom = 2 * fma(s,s,1)
//   num   = fma(-((2*p1)*p2), c, fma(p1,p1, 2*(p2*p2)))
//   T     = num / denom
//   H     = fma(10, (1-c1)+(1-c2), T)
__device__ __forceinline__ float ham_f(float p1, float p2,
                                       float s, float c,
                                       float c1, float c2)
{
    float denom = __fmul_rn(2.0f, fmaf(s, s, 1.0f));
    float t2    = __fmul_rn(2.0f, __fmul_rn(p2, p2));
    float t3    = __fmul_rn(__fmul_rn(2.0f, p1), p2);
    float num   = fmaf(-t3, c, fmaf(p1, p1, t2));
    float T     = __fdiv_rn(num, denom);
    float vw    = __fadd_rn(__fsub_rn(1.0f, c1), __fsub_rn(1.0f, c2));
    return fmaf(10.0f, vw, T);
}

// dH/dq by central differences (fresh glibc trig per q-perturbation).
__device__ __forceinline__ void grads_q(float q1, float q2, float p1, float p2,
                                        float c1b, float c2b,
                                        float* g1, float* g2)
{
    float s, c;

    float q1p = __fadd_rn(q1, EPS_F);
    glibc_sincosf(__fsub_rn(q1p, q2), &s, &c);
    float Hp1 = ham_f(p1, p2, s, c, glibc_cosf(q1p), c2b);

    float q1m = __fsub_rn(q1, EPS_F);
    glibc_sincosf(__fsub_rn(q1m, q2), &s, &c);
    float Hm1 = ham_f(p1, p2, s, c, glibc_cosf(q1m), c2b);

    *g1 = __fdiv_rn(__fsub_rn(Hp1, Hm1), TWO_EPS_F);

    float q2p = __fadd_rn(q2, EPS_F);
    glibc_sincosf(__fsub_rn(q1, q2p), &s, &c);
    float Hp2 = ham_f(p1, p2, s, c, c1b, glibc_cosf(q2p));

    float q2m = __fsub_rn(q2, EPS_F);
    glibc_sincosf(__fsub_rn(q1, q2m), &s, &c);
    float Hm2 = ham_f(p1, p2, s, c, c1b, glibc_cosf(q2m));

    *g2 = __fdiv_rn(__fsub_rn(Hp2, Hm2), TWO_EPS_F);
}

// dH/dp: q untouched -> base trig bits identical, reuse.
__device__ __forceinline__ void grads_p(float p1, float p2,
                                        float s, float c, float c1, float c2,
                                        float* g1, float* g2)
{
    float Hp1 = ham_f(__fadd_rn(p1, EPS_F), p2, s, c, c1, c2);
    float Hm1 = ham_f(__fsub_rn(p1, EPS_F), p2, s, c, c1, c2);
    *g1 = __fdiv_rn(__fsub_rn(Hp1, Hm1), TWO_EPS_F);

    float Hp2 = ham_f(p1, __fadd_rn(p2, EPS_F), s, c, c1, c2);
    float Hm2 = ham_f(p1, __fsub_rn(p2, EPS_F), s, c, c1, c2);
    *g2 = __fdiv_rn(__fsub_rn(Hp2, Hm2), TWO_EPS_F);
}

// jnp floor-mod angle normalize (cost path).
__device__ __forceinline__ float anorm(float th)
{
    float t = __fadd_rn(th, PI_F);
    float r = fmodf(t, TWO_PI_F);
    if (r < 0.0f) r = __fadd_rn(r, TWO_PI_F);
    return __fsub_rn(r, PI_F);
}

__global__ void __launch_bounds__(256)
imagination_mpc_kernel(const float* __restrict__ q0,
                       const float* __restrict__ p0,
                       const float* __restrict__ actions,
                       const float* __restrict__ target,
                       float* __restrict__ out,
                       int n)
{
    int i = blockIdx.x * blockDim.x + threadIdx.x;
    if (i >= n) return;

    float q1 = q0[2 * i], q2 = q0[2 * i + 1];
    float p1 = p0[2 * i], p2 = p0[2 * i + 1];
    float tg1 = target[0], tg2 = target[1];
    const float* arow = actions + (long long)i * T_STEPS;

    // base trig at initial q
    float sb, cb;
    glibc_sincosf(__fsub_rn(q1, q2), &sb, &cb);
    float c1b = glibc_cosf(q1), c2b = glibc_cosf(q2);

    float run = 0.0f;

#pragma unroll 1
    for (int t = 0; t < T_STEPS; t++) {
        float a = __ldg(&arow[t]);

        // ---- running cost (elementwise adds -> first-operand fusion) ----
        {
            float e1  = anorm(__fsub_rn(q1, tg1));
            float e2  = anorm(__fsub_rn(q2, tg2));
            float pos = fmaf(e1, e1, __fmul_rn(e2, e2));
            float vel = fmaf(p1, p1, __fmul_rn(p2, p2));
            float asq = __fmul_rn(a, a);
            float term_t = fmaf(0.01f, asq, __fadd_rn(pos, vel));
            run = __fadd_rn(run, term_t);
        }

        // ---- symplectic step ----
        float gq1, gq2, gp1, gp2;
        grads_q(q1, q2, p1, p2, c1b, c2b, &gq1, &gq2);
        grads_p(p1, p2, sb, cb, c1b, c2b, &gp1, &gp2);

        float ph1 = fmaf(-HALF_DT_FR_F, gp1, fmaf(-HALF_DT_F, gq1, p1));
        float ph2 = fmaf(-HALF_DT_FR_F, gp2, fmaf(-HALF_DT_F, gq2, p2));

        float gm1, gm2;
        grads_p(ph1, ph2, sb, cb, c1b, c2b, &gm1, &gm2);

        float qn1 = fmaf(DT_F, gm1, q1);
        float qn2 = fmaf(DT_F, gm2, q2);

        float sbn, cbn;
        glibc_sincosf(__fsub_rn(qn1, qn2), &sbn, &cbn);
        float c1n = glibc_cosf(qn1), c2n = glibc_cosf(qn2);

        float hq1, hq2, hp1, hp2;
        grads_q(qn1, qn2, ph1, ph2, c1n, c2n, &hq1, &hq2);
        grads_p(ph1, ph2, sbn, cbn, c1n, c2n, &hp1, &hp2);

        float pn1 = fmaf(-HALF_DT_FR_F, hp1, fmaf(-HALF_DT_F, hq1, ph1));
        float pn2 = fmaf(-HALF_DT_FR_F, hp2, fmaf(-HALF_DT_F, hq2, ph2));
        pn2 = fmaf(a, DT_F, pn2);

        q1 = qn1; q2 = qn2; p1 = pn1; p2 = pn2;
        sb = sbn; cb = cbn; c1b = c1n; c2b = c2n;
    }

    // ---- terminal cost (reduce-based sums -> SECOND-operand fusion:
    //      fadd(fadd(+0, e1*e1), fmul(e2,e2)) -> fma(e2,e2, e1*e1)) ----
    float e1 = anorm(__fsub_rn(q1, tg1));
    float e2 = anorm(__fsub_rn(q2, tg2));
    float pos_sum = fmaf(e2, e2, __fmul_rn(e1, e1));
    float vel_sum = fmaf(p2, p2, __fmul_rn(p1, p1));
    float term = fmaf(10.0f, pos_sum, vel_sum);

    out[i] = __fadd_rn(run, term);
}

extern "C" void kernel_launch(void* const* d_in, const int* in_sizes, int n_in,
                              void* d_out, int out_size)
{
    const float* q0      = (const float*)d_in[0];
    const float* p0      = (const float*)d_in[1];
    const float* actions = (const float*)d_in[2];
    const float* target  = (const float*)d_in[3];
    float* out = (float*)d_out;

    int n = in_sizes[0] / 2;
    int threads = 256;
    int blocks = (n + threads - 1) / threads;
    imagination_mpc_kernel<<<blocks, threads>>>(q0, p0, actions, target, out, n);
}

// round 8
// speedup vs baseline: 1.6643x; 1.6643x over previous
#include <cuda_runtime.h>
#include <stdint.h>

// ---------------------------------------------------------------------------
// ImaginationMPCV2 — bit-exact to jax on Grace CPU (aarch64): XLA:CPU strict
// middle-end + backend FPOpFusion::Fast (aarch64 DAG fmadd fusion), trig =
// glibc optimized-routines sinf/cosf (TOINT_INTRINSICS).
//
// R8 perf changes (all bit-preserving):
//  * Branchless unified trig band path: for |x| < pi/4 the band path
//    (n=0, xr = fma(-0,hpi,x) = x) produces bitwise the small-path results,
//    so one straight-line path serves all |x| < 120 -> no warp divergence,
//    no BSSY/BSYNC, both polys always evaluated, sign/poly select via
//    SEL + sign-bit XOR (matches glibc's negate incl. -0).
//  * n = F2I_rn(r); rr = I2F(n): identical values, off the FP64-FMA pipe.
//  * 128-thread blocks -> finer wave granularity (smaller tail).
// ---------------------------------------------------------------------------

#define EPS_F          1e-5f
#define TWO_EPS_F      2e-5f
#define DT_F           0.02f
#define HALF_DT_F      0.01f
#define HALF_DT_FR_F   0.001f
#define PI_F           3.14159265358979323846f
#define TWO_PI_F       6.28318530717958647692f
#define T_STEPS        100

// ---- glibc sincosf constants (optimized-routines, table entry 0) ----
#define HPI_INV_D  0x1.45F306DC9C883p-1   // 2/pi
#define HPI_D      0x1.921FB54442D18p0    // pi/2
#define S1_D      -0x1.555545995a603p-3
#define S2_D       0x1.1107605230bc4p-7
#define S3_D      -0x1.994eb3774cf24p-13
#define C0_D       0x1p0
#define C1_D      -0x1.ffffffd0c621cp-2
#define C2_D       0x1.55553e1068f19p-5
#define C3_D      -0x1.6c087e89a359dp-10
#define C4_D       0x1.99343027bf8c3p-16

// sine-branch polynomial magnitude (glibc sinf_poly, fma-contracted).
__device__ __forceinline__ float sinpoly_mag(double xr, double x2)
{
    double x3 = xr * x2;
    double s1 = fma(x2, S3_D, S2_D);
    double x7 = x3 * x2;
    double s  = fma(x3, S1_D, xr);
    return (float)fma(x7, s1, s);
}

// cosine-branch polynomial magnitude (entry-0 coefficients).
__device__ __forceinline__ float cospoly_mag(double x2)
{
    double x4 = x2 * x2;
    double c2 = fma(x2, C4_D, C3_D);
    double c1 = fma(x2, C1_D, C0_D);
    double x6 = x4 * x2;
    double c  = fma(x4, C2_D, c1);
    return (float)fma(x6, c2, c);
}

__device__ __forceinline__ float sign_xor(float v, uint32_t bit31)
{
    return __uint_as_float(__float_as_uint(v) ^ bit31);
}

// Unified branchless glibc sinf+cosf (bit-exact for |y| < 120; for
// |y| < pi/4 the reduction yields n=0, xr=x -> identical to the fast paths,
// including the tiny |y| < 2^-12 case, which rounds to (y, 1.0f) here too).
__device__ __forceinline__ void glibc_sincosf(float y, float* so, float* co)
{
    double x = (double)y;
    uint32_t ax = __float_as_uint(y) & 0x7fffffffu;

    if (ax >= 0x42F00000u) {          // |y| >= 120: unreachable cold fallback
        double ds, dc;
        sincos(x, &ds, &dc);
        *so = (float)ds; *co = (float)dc;
        return;
    }

    // reduce_fast (TOINT_INTRINSICS): ties-to-even round of x*(2/pi).
    double r  = x * HPI_INV_D;
    int    n  = __double2int_rn(r);   // fcvtns (ties-to-even)
    double rr = (double)n;            // == rint(r), off the FP64-FMA pipe
    double xr = fma(-rr, HPI_D, x);

    double x2 = xr * xr;
    float  sm = sinpoly_mag(xr, x2);
    float  cm = cospoly_mag(x2);

    // sinf: n odd -> cos-poly, sign = n&2 ; n even -> sin-poly, sign = n&2
    // cosf: n odd -> sin-poly ; n even -> cos-poly ; sign = (n+1)&2 (both)
    int odd = n & 1;
    float smag = odd ? cm : sm;
    float cmag = odd ? sm : cm;
    *so = sign_xor(smag, ((uint32_t)(n & 2)) << 30);
    *co = sign_xor(cmag, ((uint32_t)((n + 1) & 2)) << 30);
}

// cos-only wrapper (same unified path; sin side discarded by DCE where
// possible — both polys are required for bit-exact cos anyway).
__device__ __forceinline__ float glibc_cosf(float y)
{
    float s, c;
    glibc_sincosf(y, &s, &c);
    return c;
}

// ---- Hamiltonian with aarch64-backend fusion pattern ----
__device__ __forceinline__ float ham_f(float p1, float p2,
                                       float s, float c,
                                       float c1, float c2)
{
    float denom = __fmul_rn(2.0f, fmaf(s, s, 1.0f));
    float t2    = __fmul_rn(2.0f, __fmul_rn(p2, p2));
    float t3    = __fmul_rn(__fmul_rn(2.0f, p1), p2);
    float num   = fmaf(-t3, c, fmaf(p1, p1, t2));
    float T     = __fdiv_rn(num, denom);
    float vw    = __fadd_rn(__fsub_rn(1.0f, c1), __fsub_rn(1.0f, c2));
    return fmaf(10.0f, vw, T);
}

// dH/dq by central differences (fresh glibc trig per q-perturbation).
__device__ __forceinline__ void grads_q(float q1, float q2, float p1, float p2,
                                        float c1b, float c2b,
                                        float* g1, float* g2)
{
    float sa, ca, sbq, cbq, sc, cc, sd, cd;

    float q1p = __fadd_rn(q1, EPS_F);
    float q1m = __fsub_rn(q1, EPS_F);
    float q2p = __fadd_rn(q2, EPS_F);
    float q2m = __fsub_rn(q2, EPS_F);

    // 8 independent trig evaluations -> deep FP64 ILP
    glibc_sincosf(__fsub_rn(q1p, q2), &sa, &ca);
    glibc_sincosf(__fsub_rn(q1m, q2), &sbq, &cbq);
    glibc_sincosf(__fsub_rn(q1, q2p), &sc, &cc);
    glibc_sincosf(__fsub_rn(q1, q2m), &sd, &cd);
    float cq1p = glibc_cosf(q1p);
    float cq1m = glibc_cosf(q1m);
    float cq2p = glibc_cosf(q2p);
    float cq2m = glibc_cosf(q2m);

    float Hp1 = ham_f(p1, p2, sa, ca, cq1p, c2b);
    float Hm1 = ham_f(p1, p2, sbq, cbq, cq1m, c2b);
    *g1 = __fdiv_rn(__fsub_rn(Hp1, Hm1), TWO_EPS_F);

    float Hp2 = ham_f(p1, p2, sc, cc, c1b, cq2p);
    float Hm2 = ham_f(p1, p2, sd, cd, c1b, cq2m);
    *g2 = __fdiv_rn(__fsub_rn(Hp2, Hm2), TWO_EPS_F);
}

// dH/dp: q untouched -> base trig bits identical, reuse.
__device__ __forceinline__ void grads_p(float p1, float p2,
                                        float s, float c, float c1, float c2,
                                        float* g1, float* g2)
{
    float Hp1 = ham_f(__fadd_rn(p1, EPS_F), p2, s, c, c1, c2);
    float Hm1 = ham_f(__fsub_rn(p1, EPS_F), p2, s, c, c1, c2);
    *g1 = __fdiv_rn(__fsub_rn(Hp1, Hm1), TWO_EPS_F);

    float Hp2 = ham_f(p1, __fadd_rn(p2, EPS_F), s, c, c1, c2);
    float Hm2 = ham_f(p1, __fsub_rn(p2, EPS_F), s, c, c1, c2);
    *g2 = __fdiv_rn(__fsub_rn(Hp2, Hm2), TWO_EPS_F);
}

// jnp floor-mod angle normalize (cost path).
__device__ __forceinline__ float anorm(float th)
{
    float t = __fadd_rn(th, PI_F);
    float r = fmodf(t, TWO_PI_F);
    if (r < 0.0f) r = __fadd_rn(r, TWO_PI_F);
    return __fsub_rn(r, PI_F);
}

__global__ void __launch_bounds__(128)
imagination_mpc_kernel(const float* __restrict__ q0,
                       const float* __restrict__ p0,
                       const float* __restrict__ actions,
                       const float* __restrict__ target,
                       float* __restrict__ out,
                       int n)
{
    int i = blockIdx.x * blockDim.x + threadIdx.x;
    if (i >= n) return;

    float q1 = q0[2 * i], q2 = q0[2 * i + 1];
    float p1 = p0[2 * i], p2 = p0[2 * i + 1];
    float tg1 = target[0], tg2 = target[1];
    const float* arow = actions + (long long)i * T_STEPS;

    // base trig at initial q
    float sb, cb;
    glibc_sincosf(__fsub_rn(q1, q2), &sb, &cb);
    float c1b = glibc_cosf(q1), c2b = glibc_cosf(q2);

    float run = 0.0f;

#pragma unroll 1
    for (int t = 0; t < T_STEPS; t++) {
        float a = __ldg(&arow[t]);

        // ---- running cost (elementwise adds -> first-operand fusion) ----
        {
            float e1  = anorm(__fsub_rn(q1, tg1));
            float e2  = anorm(__fsub_rn(q2, tg2));
            float pos = fmaf(e1, e1, __fmul_rn(e2, e2));
            float vel = fmaf(p1, p1, __fmul_rn(p2, p2));
            float asq = __fmul_rn(a, a);
            float term_t = fmaf(0.01f, asq, __fadd_rn(pos, vel));
            run = __fadd_rn(run, term_t);
        }

        // ---- symplectic step ----
        float gq1, gq2, gp1, gp2;
        grads_q(q1, q2, p1, p2, c1b, c2b, &gq1, &gq2);
        grads_p(p1, p2, sb, cb, c1b, c2b, &gp1, &gp2);

        float ph1 = fmaf(-HALF_DT_FR_F, gp1, fmaf(-HALF_DT_F, gq1, p1));
        float ph2 = fmaf(-HALF_DT_FR_F, gp2, fmaf(-HALF_DT_F, gq2, p2));

        float gm1, gm2;
        grads_p(ph1, ph2, sb, cb, c1b, c2b, &gm1, &gm2);

        float qn1 = fmaf(DT_F, gm1, q1);
        float qn2 = fmaf(DT_F, gm2, q2);

        float sbn, cbn;
        glibc_sincosf(__fsub_rn(qn1, qn2), &sbn, &cbn);
        float c1n = glibc_cosf(qn1), c2n = glibc_cosf(qn2);

        float hq1, hq2, hp1, hp2;
        grads_q(qn1, qn2, ph1, ph2, c1n, c2n, &hq1, &hq2);
        grads_p(ph1, ph2, sbn, cbn, c1n, c2n, &hp1, &hp2);

        float pn1 = fmaf(-HALF_DT_FR_F, hp1, fmaf(-HALF_DT_F, hq1, ph1));
        float pn2 = fmaf(-HALF_DT_FR_F, hp2, fmaf(-HALF_DT_F, hq2, ph2));
        pn2 = fmaf(a, DT_F, pn2);

        q1 = qn1; q2 = qn2; p1 = pn1; p2 = pn2;
        sb = sbn; cb = cbn; c1b = c1n; c2b = c2n;
    }

    // ---- terminal cost (reduce-based sums -> second-operand fusion) ----
    float e1 = anorm(__fsub_rn(q1, tg1));
    float e2 = anorm(__fsub_rn(q2, tg2));
    float pos_sum = fmaf(e2, e2, __fmul_rn(e1, e1));
    float vel_sum = fmaf(p2, p2, __fmul_rn(p1, p1));
    float term = fmaf(10.0f, pos_sum, vel_sum);

    out[i] = __fadd_rn(run, term);
}

extern "C" void kernel_launch(void* const* d_in, const int* in_sizes, int n_in,
                              void* d_out, int out_size)
{
    const float* q0      = (const float*)d_in[0];
    const float* p0      = (const float*)d_in[1];
    const float* actions = (const float*)d_in[2];
    const float* target  = (const float*)d_in[3];
    float* out = (float*)d_out;

    int n = in_sizes[0] / 2;
    int threads = 128;
    int blocks = (n + threads - 1) / threads;
    imagination_mpc_kernel<<<blocks, threads>>>(q0, p0, actions, target, out, n);
}